// round 3
// baseline (speedup 1.0000x reference)
#include <cuda_runtime.h>
#include <cuda_bf16.h>
#include <math.h>

#define T_LEN 8192
#define DM    1536
#define NH    16
#define NKV   4
#define HD    96
#define KVW   (NKV*HD)   // 384
#define QW    (NH*HD)    // 1536
#define W2    256

// ---------------- scratch (device globals; no allocation allowed) ----------
__device__ float g_qs[(size_t)T_LEN*QW];
__device__ float g_qg[(size_t)T_LEN*QW];
__device__ float g_ks[(size_t)T_LEN*KVW];
__device__ float g_vs[(size_t)T_LEN*KVW];
__device__ float g_kg[(size_t)T_LEN*KVW];
__device__ float g_vg[(size_t)T_LEN*KVW];
__device__ float g_ctx[(size_t)T_LEN*QW];

// ---------------- SGEMM: C[M,N] = A[M,K] @ B[K,N], row-major, fp32 --------
// 128x128 block tile, BK=16, 256 threads, 8x8 per thread (two 4x4 quadrants)
__global__ __launch_bounds__(256)
void sgemm_kernel(const float* __restrict__ A, const float* __restrict__ B,
                  float* __restrict__ C, int M, int N, int K) {
    __shared__ float As[16][132];
    __shared__ float Bs[16][132];
    int tid = threadIdx.x;
    int tx = tid & 15;          // 0..15 (N dim)
    int ty = tid >> 4;          // 0..15 (M dim)
    int row0 = blockIdx.y * 128;
    int col0 = blockIdx.x * 128;

    float c[8][8];
#pragma unroll
    for (int i = 0; i < 8; i++)
#pragma unroll
        for (int j = 0; j < 8; j++) c[i][j] = 0.f;

    for (int k0 = 0; k0 < K; k0 += 16) {
        // load A tile (128 rows x 16 k), store transposed As[k][row]
#pragma unroll
        for (int i = 0; i < 2; i++) {
            int f  = tid + 256 * i;       // 0..511 float4 slots
            int r  = f >> 2;              // 0..127
            int kq = (f & 3) * 4;         // 0,4,8,12
            float4 v = *(const float4*)&A[(size_t)(row0 + r) * K + k0 + kq];
            As[kq + 0][r] = v.x; As[kq + 1][r] = v.y;
            As[kq + 2][r] = v.z; As[kq + 3][r] = v.w;
        }
        // load B tile (16 k x 128 cols)
#pragma unroll
        for (int i = 0; i < 2; i++) {
            int f  = tid + 256 * i;
            int r  = f >> 5;              // 0..15
            int c4 = (f & 31) * 4;        // 0..124
            *(float4*)&Bs[r][c4] = *(const float4*)&B[(size_t)(k0 + r) * N + col0 + c4];
        }
        __syncthreads();
#pragma unroll
        for (int kk = 0; kk < 16; kk++) {
            float4 a0 = *(float4*)&As[kk][ty * 4];
            float4 a1 = *(float4*)&As[kk][64 + ty * 4];
            float4 b0 = *(float4*)&Bs[kk][tx * 4];
            float4 b1 = *(float4*)&Bs[kk][64 + tx * 4];
            float a[8] = {a0.x, a0.y, a0.z, a0.w, a1.x, a1.y, a1.z, a1.w};
            float b[8] = {b0.x, b0.y, b0.z, b0.w, b1.x, b1.y, b1.z, b1.w};
#pragma unroll
            for (int i = 0; i < 8; i++)
#pragma unroll
                for (int j = 0; j < 8; j++) c[i][j] += a[i] * b[j];
        }
        __syncthreads();
    }
    // epilogue
#pragma unroll
    for (int i = 0; i < 8; i++) {
        int r = row0 + ((i < 4) ? (ty * 4 + i) : (64 + ty * 4 + i - 4));
        float4 v0 = make_float4(c[i][0], c[i][1], c[i][2], c[i][3]);
        float4 v1 = make_float4(c[i][4], c[i][5], c[i][6], c[i][7]);
        *(float4*)&C[(size_t)r * N + col0 + tx * 4]      = v0;
        *(float4*)&C[(size_t)r * N + col0 + 64 + tx * 4] = v1;
    }
}

// ---------------- RoPE (interleaved pairs), in place on [T, H, HD] --------
__global__ void rope_kernel(float* __restrict__ x,
                            const float* __restrict__ cosf,
                            const float* __restrict__ sinf, int H) {
    int idx = blockIdx.x * blockDim.x + threadIdx.x;   // pair index
    int total = T_LEN * H * (HD / 2);
    if (idx >= total) return;
    int p = idx % (HD / 2);
    int h = (idx / (HD / 2)) % H;
    int t = idx / ((HD / 2) * H);
    float c = cosf[t * (HD / 2) + p];
    float s = sinf[t * (HD / 2) + p];
    float* base = x + ((size_t)t * H + h) * HD + 2 * p;
    float xe = base[0], xo = base[1];
    base[0] = xe * c - xo * s;
    base[1] = xe * s + xo * c;
}

// ---------------- local sliding-window attention + 1 global token ---------
// block = (128 queries, 1 head); thread = 1 query; flash-style online softmax
__global__ __launch_bounds__(128)
void local_attn_kernel(const float* __restrict__ qs, const float* __restrict__ ks,
                       const float* __restrict__ vs, const float* __restrict__ kg,
                       const float* __restrict__ vg, float* __restrict__ ctx) {
    extern __shared__ float smem[];
    float* Ks = smem;                 // [128][96]
    float* Vs = smem + 128 * HD;      // [128][96]
    int tid = threadIdx.x;
    int h   = blockIdx.y;
    int kvh = h >> 2;
    int q0  = blockIdx.x * 128;
    int t   = q0 + tid;

    float q[HD];
#pragma unroll
    for (int d = 0; d < HD; d += 4) {
        float4 v = *(const float4*)&qs[((size_t)t * NH + h) * HD + d];
        q[d] = v.x; q[d + 1] = v.y; q[d + 2] = v.z; q[d + 3] = v.w;
    }
    const float scale = rsqrtf((float)HD);
    float m = -1e30f, l = 0.f;
    float acc[HD];
#pragma unroll
    for (int d = 0; d < HD; d++) acc[d] = 0.f;

    // window keys span [q0 - W2, q0 + 128): three 128-key tiles
    for (int kt = 0; kt < 3; kt++) {
        int kstart = q0 - W2 + kt * 128;
        int krow = kstart + tid;
        if (krow >= 0 && krow < T_LEN) {
#pragma unroll
            for (int d = 0; d < HD; d += 4) {
                *(float4*)&Ks[tid * HD + d] = *(const float4*)&ks[((size_t)krow * NKV + kvh) * HD + d];
                *(float4*)&Vs[tid * HD + d] = *(const float4*)&vs[((size_t)krow * NKV + kvh) * HD + d];
            }
        }
        __syncthreads();
        for (int j = 0; j < 128; j++) {
            int kpos = kstart + j;
            bool valid = (kpos >= 1) && (kpos <= t) && (kpos >= t - W2);
            if (valid) {
                float s = 0.f;
#pragma unroll
                for (int d = 0; d < HD; d += 4) {
                    float4 kv = *(float4*)&Ks[j * HD + d];
                    s += q[d] * kv.x + q[d + 1] * kv.y + q[d + 2] * kv.z + q[d + 3] * kv.w;
                }
                s *= scale;
                if (s > m) {
                    float corr = __expf(m - s);
                    m = s; l *= corr;
#pragma unroll
                    for (int d = 0; d < HD; d++) acc[d] *= corr;
                }
                float p = __expf(s - m);
                l += p;
#pragma unroll
                for (int d = 0; d < HD; d += 4) {
                    float4 vv = *(float4*)&Vs[j * HD + d];
                    acc[d] += p * vv.x; acc[d + 1] += p * vv.y;
                    acc[d + 2] += p * vv.z; acc[d + 3] += p * vv.w;
                }
            }
        }
        __syncthreads();
    }
    // global key (position 0, kg/vg projections); always valid (0 <= t)
    {
        float s = 0.f;
#pragma unroll
        for (int d = 0; d < HD; d++) s += q[d] * kg[(size_t)kvh * HD + d];
        s *= scale;
        if (s > m) {
            float corr = __expf(m - s);
            m = s; l *= corr;
#pragma unroll
            for (int d = 0; d < HD; d++) acc[d] *= corr;
        }
        float p = __expf(s - m);
        l += p;
#pragma unroll
        for (int d = 0; d < HD; d++) acc[d] += p * vg[(size_t)kvh * HD + d];
    }
    float inv = 1.f / l;
#pragma unroll
    for (int d = 0; d < HD; d += 4) {
        float4 o = make_float4(acc[d] * inv, acc[d + 1] * inv, acc[d + 2] * inv, acc[d + 3] * inv);
        *(float4*)&ctx[((size_t)t * NH + h) * HD + d] = o;
    }
}

// ---------------- global row: q@pos0 (qg) over all T kg keys --------------
__global__ __launch_bounds__(192)
void global_row_kernel(const float* __restrict__ qg, const float* __restrict__ kg,
                       const float* __restrict__ vg, float* __restrict__ ctx) {
    __shared__ float p[T_LEN];     // 32 KB
    __shared__ float red[256];
    int h = blockIdx.x, kvh = h >> 2, tid = threadIdx.x;
    float q[HD];
#pragma unroll
    for (int d = 0; d < HD; d++) q[d] = qg[(size_t)h * HD + d];
    const float scale = rsqrtf((float)HD);

    float lm = -1e30f;
    for (int t = tid; t < T_LEN; t += 192) {
        float s = 0.f;
#pragma unroll
        for (int d = 0; d < HD; d++) s += q[d] * kg[((size_t)t * NKV + kvh) * HD + d];
        s *= scale;
        p[t] = s;
        lm = fmaxf(lm, s);
    }
    red[tid] = lm;
    if (tid < 64) red[192 + tid] = -1e30f;
    __syncthreads();
    for (int o = 128; o > 0; o >>= 1) {
        if (tid < o) red[tid] = fmaxf(red[tid], red[tid + o]);
        __syncthreads();
    }
    float m = red[0];
    __syncthreads();

    float ll = 0.f;
    for (int t = tid; t < T_LEN; t += 192) {
        float e = __expf(p[t] - m);
        p[t] = e;
        ll += e;
    }
    red[tid] = ll;
    if (tid < 64) red[192 + tid] = 0.f;
    __syncthreads();
    for (int o = 128; o > 0; o >>= 1) {
        if (tid < o) red[tid] += red[tid + o];
        __syncthreads();
    }
    float inv = 1.f / red[0];
    __syncthreads();

    int d = tid % 96, g = tid / 96;   // g in {0,1}
    float acc0 = 0.f, acc1 = 0.f, acc2 = 0.f, acc3 = 0.f;
    for (int t = g; t < T_LEN; t += 8) {
        acc0 += p[t]     * vg[((size_t)t       * NKV + kvh) * HD + d];
        acc1 += p[t + 2] * vg[((size_t)(t + 2) * NKV + kvh) * HD + d];
        acc2 += p[t + 4] * vg[((size_t)(t + 4) * NKV + kvh) * HD + d];
        acc3 += p[t + 6] * vg[((size_t)(t + 6) * NKV + kvh) * HD + d];
    }
    red[tid] = acc0 + acc1 + acc2 + acc3;
    __syncthreads();
    if (g == 0) ctx[(size_t)h * HD + d] = (red[d] + red[96 + d]) * inv;
}

// ---------------- launch ---------------------------------------------------
extern "C" void kernel_launch(void* const* d_in, const int* in_sizes, int n_in,
                              void* d_out, int out_size) {
    const float* x    = (const float*)d_in[0];
    const float* cosf = (const float*)d_in[1];
    const float* sinf = (const float*)d_in[2];
    // d_in[3] = position_ids (arange, unused)
    const float* W_qs = (const float*)d_in[4];
    const float* W_ks = (const float*)d_in[5];
    const float* W_vs = (const float*)d_in[6];
    const float* W_qg = (const float*)d_in[7];
    const float* W_kg = (const float*)d_in[8];
    const float* W_vg = (const float*)d_in[9];
    const float* W_o  = (const float*)d_in[10];
    float* out = (float*)d_out;

    float *qs, *ks, *vs, *qg, *kg, *vg, *ctx;
    cudaGetSymbolAddress((void**)&qs,  g_qs);
    cudaGetSymbolAddress((void**)&ks,  g_ks);
    cudaGetSymbolAddress((void**)&vs,  g_vs);
    cudaGetSymbolAddress((void**)&qg,  g_qg);
    cudaGetSymbolAddress((void**)&kg,  g_kg);
    cudaGetSymbolAddress((void**)&vg,  g_vg);
    cudaGetSymbolAddress((void**)&ctx, g_ctx);

    dim3 blk(256);
    dim3 gWide(QW / 128, T_LEN / 128);    // (12, 64)
    dim3 gNar(KVW / 128, T_LEN / 128);    // (3, 64)

    sgemm_kernel<<<gWide, blk>>>(x, W_qs, qs, T_LEN, QW, DM);
    sgemm_kernel<<<gNar,  blk>>>(x, W_ks, ks, T_LEN, KVW, DM);
    sgemm_kernel<<<gNar,  blk>>>(x, W_vs, vs, T_LEN, KVW, DM);
    sgemm_kernel<<<gWide, blk>>>(x, W_qg, qg, T_LEN, QW, DM);
    sgemm_kernel<<<gNar,  blk>>>(x, W_kg, kg, T_LEN, KVW, DM);
    sgemm_kernel<<<gNar,  blk>>>(x, W_vg, vg, T_LEN, KVW, DM);

    int pairs16 = T_LEN * NH * (HD / 2);
    int pairs4  = T_LEN * NKV * (HD / 2);
    rope_kernel<<<(pairs16 + 255) / 256, 256>>>(qs, cosf, sinf, NH);
    rope_kernel<<<(pairs4  + 255) / 256, 256>>>(ks, cosf, sinf, NKV);
    rope_kernel<<<(pairs16 + 255) / 256, 256>>>(qg, cosf, sinf, NH);
    rope_kernel<<<(pairs4  + 255) / 256, 256>>>(kg, cosf, sinf, NKV);

    int smem_attn = 2 * 128 * HD * (int)sizeof(float);  // 98304
    cudaFuncSetAttribute(local_attn_kernel,
                         cudaFuncAttributeMaxDynamicSharedMemorySize, smem_attn);
    local_attn_kernel<<<dim3(T_LEN / 128, NH), 128, smem_attn>>>(qs, ks, vs, kg, vg, ctx);

    global_row_kernel<<<NH, 192>>>(qg, kg, vg, ctx);

    sgemm_kernel<<<gWide, blk>>>(ctx, W_o, out, T_LEN, QW, DM);
}

// round 5
// speedup vs baseline: 1.7678x; 1.7678x over previous
#include <cuda_runtime.h>
#include <cuda_bf16.h>
#include <math.h>

#define T_LEN 8192
#define DM    1536
#define NH    16
#define NKV   4
#define HD    96
#define KVW   (NKV*HD)   // 384
#define QW    (NH*HD)    // 1536
#define W2    256

// ---------------- scratch (device globals; no allocation allowed) ----------
__device__ float g_qs[(size_t)T_LEN*QW];
__device__ float g_ks[(size_t)T_LEN*KVW];
__device__ float g_vs[(size_t)T_LEN*KVW];
__device__ float g_kg[(size_t)T_LEN*KVW];
__device__ float g_vg[(size_t)T_LEN*KVW];
__device__ float g_ctx[(size_t)T_LEN*QW];
__device__ float g_qg0[QW];

// ---------------- helpers ---------------------------------------------------
__device__ __forceinline__ unsigned f2tf(float x) {
    unsigned u; asm("cvt.rna.tf32.f32 %0, %1;" : "=r"(u) : "f"(x)); return u;
}
__device__ __forceinline__ void mma_tf32(float c[4], const unsigned a[4], const unsigned b[2]) {
    asm volatile("mma.sync.aligned.m16n8k8.row.col.f32.tf32.tf32.f32 "
        "{%0,%1,%2,%3}, {%4,%5,%6,%7}, {%8,%9}, {%0,%1,%2,%3};"
        : "+f"(c[0]), "+f"(c[1]), "+f"(c[2]), "+f"(c[3])
        : "r"(a[0]), "r"(a[1]), "r"(a[2]), "r"(a[3]), "r"(b[0]), "r"(b[1]));
}

// ---------------- TF32 GEMM: C[M,N] = A[M,K] @ B[K,N], row-major -----------
// 128x128 block tile, BK=32, 256 threads (8 warps, 4x2), warp tile 32x64.
#define SPAD 8
#define SW (128 + SPAD)
__global__ __launch_bounds__(256)
void tf32_gemm(const float* __restrict__ A, const float* __restrict__ B,
               float* __restrict__ C, int M, int N, int K) {
    __shared__ unsigned As[32][SW];   // [k][m]
    __shared__ unsigned Bs[32][SW];   // [k][n]
    int tid = threadIdx.x;
    int lane = tid & 31, warp = tid >> 5;
    int wm = (warp >> 1) * 32;        // warp m-offset (0,32,64,96)
    int wn = (warp & 1) * 64;         // warp n-offset (0,64)
    int row0 = blockIdx.y * 128, col0 = blockIdx.x * 128;
    int gid = lane >> 2, qid = lane & 3;

    float c[2][8][4];
#pragma unroll
    for (int mt = 0; mt < 2; mt++)
#pragma unroll
        for (int nt = 0; nt < 8; nt++)
#pragma unroll
            for (int i = 0; i < 4; i++) c[mt][nt][i] = 0.f;

    for (int k0 = 0; k0 < K; k0 += 32) {
        // A tile: 128 rows x 32 k -> As[k][m] transposed (1024 float4 slots)
#pragma unroll
        for (int i = 0; i < 4; i++) {
            int f  = tid + 256 * i;
            int r  = f >> 3;            // 0..127 row
            int kq = (f & 7) * 4;       // 0..28
            float4 v = *(const float4*)&A[(size_t)(row0 + r) * K + k0 + kq];
            As[kq + 0][r] = f2tf(v.x); As[kq + 1][r] = f2tf(v.y);
            As[kq + 2][r] = f2tf(v.z); As[kq + 3][r] = f2tf(v.w);
        }
        // B tile: 32 k x 128 cols -> Bs[k][n] (1024 float4 slots)
#pragma unroll
        for (int i = 0; i < 4; i++) {
            int f  = tid + 256 * i;
            int r  = f >> 5;            // 0..31 k
            int c4 = (f & 31) * 4;      // 0..124
            float4 v = *(const float4*)&B[(size_t)(k0 + r) * N + col0 + c4];
            uint4 u = make_uint4(f2tf(v.x), f2tf(v.y), f2tf(v.z), f2tf(v.w));
            *(uint4*)&Bs[r][c4] = u;
        }
        __syncthreads();
#pragma unroll
        for (int kk = 0; kk < 4; kk++) {
            int kb = kk * 8 + qid;
            unsigned a[2][4], b[8][2];
#pragma unroll
            for (int mt = 0; mt < 2; mt++) {
                int row = wm + mt * 16 + gid;
                a[mt][0] = As[kb][row];     a[mt][1] = As[kb][row + 8];
                a[mt][2] = As[kb + 4][row]; a[mt][3] = As[kb + 4][row + 8];
            }
#pragma unroll
            for (int nt = 0; nt < 8; nt++) {
                int col = wn + nt * 8 + gid;
                b[nt][0] = Bs[kb][col]; b[nt][1] = Bs[kb + 4][col];
            }
#pragma unroll
            for (int mt = 0; mt < 2; mt++)
#pragma unroll
                for (int nt = 0; nt < 8; nt++)
                    mma_tf32(c[mt][nt], a[mt], b[nt]);
        }
        __syncthreads();
    }
    // epilogue
#pragma unroll
    for (int mt = 0; mt < 2; mt++) {
        int r = row0 + wm + mt * 16 + gid;
#pragma unroll
        for (int nt = 0; nt < 8; nt++) {
            int cc = col0 + wn + nt * 8 + 2 * qid;
            *(float2*)&C[(size_t)r * N + cc]       = make_float2(c[mt][nt][0], c[mt][nt][1]);
            *(float2*)&C[(size_t)(r + 8) * N + cc] = make_float2(c[mt][nt][2], c[mt][nt][3]);
        }
    }
}

// ---------------- qg row 0 only: out[j] = x[0,:] @ W_qg[:,j] ---------------
// (RoPE at position 0 is identity, so no rope needed.)
__global__ __launch_bounds__(256)
void qg0_kernel(const float* __restrict__ x, const float* __restrict__ W,
                float* __restrict__ out) {
    __shared__ float xs[DM];
    int j = blockIdx.x * 256 + threadIdx.x;
    for (int k = threadIdx.x; k < DM; k += 256) xs[k] = x[k];
    __syncthreads();
    float a0 = 0.f, a1 = 0.f, a2 = 0.f, a3 = 0.f;
#pragma unroll 4
    for (int k = 0; k < DM; k += 4) {
        a0 += xs[k]     * W[(size_t)k       * QW + j];
        a1 += xs[k + 1] * W[(size_t)(k + 1) * QW + j];
        a2 += xs[k + 2] * W[(size_t)(k + 2) * QW + j];
        a3 += xs[k + 3] * W[(size_t)(k + 3) * QW + j];
    }
    out[j] = (a0 + a1) + (a2 + a3);
}

// ---------------- RoPE (interleaved pairs), in place on [T, H, HD] --------
__global__ void rope_kernel(float* __restrict__ x,
                            const float* __restrict__ cosf,
                            const float* __restrict__ sinf, int H) {
    int idx = blockIdx.x * blockDim.x + threadIdx.x;   // pair index
    int total = T_LEN * H * (HD / 2);
    if (idx >= total) return;
    int p = idx % (HD / 2);
    int h = (idx / (HD / 2)) % H;
    int t = idx / ((HD / 2) * H);
    float c = cosf[t * (HD / 2) + p];
    float s = sinf[t * (HD / 2) + p];
    float* base = x + ((size_t)t * H + h) * HD + 2 * p;
    float xe = base[0], xo = base[1];
    base[0] = xe * c - xo * s;
    base[1] = xe * s + xo * c;
}

// ---------------- local sliding-window attention + 1 global token ---------
__global__ __launch_bounds__(128)
void local_attn_kernel(const float* __restrict__ qs, const float* __restrict__ ks,
                       const float* __restrict__ vs, const float* __restrict__ kg,
                       const float* __restrict__ vg, float* __restrict__ ctx) {
    extern __shared__ float smem[];
    float* Ks = smem;                 // [128][96]
    float* Vs = smem + 128 * HD;      // [128][96]
    int tid = threadIdx.x;
    int h   = blockIdx.y;
    int kvh = h >> 2;
    int q0  = blockIdx.x * 128;
    int t   = q0 + tid;

    float q[HD];
#pragma unroll
    for (int d = 0; d < HD; d += 4) {
        float4 v = *(const float4*)&qs[((size_t)t * NH + h) * HD + d];
        q[d] = v.x; q[d + 1] = v.y; q[d + 2] = v.z; q[d + 3] = v.w;
    }
    const float scale = rsqrtf((float)HD);
    float m = -1e30f, l = 0.f;
    float acc[HD];
#pragma unroll
    for (int d = 0; d < HD; d++) acc[d] = 0.f;

    // window keys span [q0 - W2, q0 + 128): three 128-key tiles
    for (int kt = 0; kt < 3; kt++) {
        int kstart = q0 - W2 + kt * 128;
        int krow = kstart + tid;
        if (krow >= 0 && krow < T_LEN) {
#pragma unroll
            for (int d = 0; d < HD; d += 4) {
                *(float4*)&Ks[tid * HD + d] = *(const float4*)&ks[((size_t)krow * NKV + kvh) * HD + d];
                *(float4*)&Vs[tid * HD + d] = *(const float4*)&vs[((size_t)krow * NKV + kvh) * HD + d];
            }
        }
        __syncthreads();
        for (int j = 0; j < 128; j++) {
            int kpos = kstart + j;
            bool valid = (kpos >= 1) && (kpos <= t) && (kpos >= t - W2);
            if (valid) {
                float s = 0.f;
#pragma unroll
                for (int d = 0; d < HD; d += 4) {
                    float4 kv = *(float4*)&Ks[j * HD + d];
                    s += q[d] * kv.x + q[d + 1] * kv.y + q[d + 2] * kv.z + q[d + 3] * kv.w;
                }
                s *= scale;
                if (s > m) {
                    float corr = __expf(m - s);
                    m = s; l *= corr;
#pragma unroll
                    for (int d = 0; d < HD; d++) acc[d] *= corr;
                }
                float p = __expf(s - m);
                l += p;
#pragma unroll
                for (int d = 0; d < HD; d += 4) {
                    float4 vv = *(float4*)&Vs[j * HD + d];
                    acc[d] += p * vv.x; acc[d + 1] += p * vv.y;
                    acc[d + 2] += p * vv.z; acc[d + 3] += p * vv.w;
                }
            }
        }
        __syncthreads();
    }
    // global key (position 0, kg/vg projections)
    {
        float s = 0.f;
#pragma unroll
        for (int d = 0; d < HD; d++) s += q[d] * kg[(size_t)kvh * HD + d];
        s *= scale;
        if (s > m) {
            float corr = __expf(m - s);
            m = s; l *= corr;
#pragma unroll
            for (int d = 0; d < HD; d++) acc[d] *= corr;
        }
        float p = __expf(s - m);
        l += p;
#pragma unroll
        for (int d = 0; d < HD; d++) acc[d] += p * vg[(size_t)kvh * HD + d];
    }
    float inv = 1.f / l;
#pragma unroll
    for (int d = 0; d < HD; d += 4) {
        float4 o = make_float4(acc[d] * inv, acc[d + 1] * inv, acc[d + 2] * inv, acc[d + 3] * inv);
        *(float4*)&ctx[((size_t)t * NH + h) * HD + d] = o;
    }
}

// ---------------- global row: q@pos0 (qg) over all T kg keys --------------
__global__ __launch_bounds__(192)
void global_row_kernel(const float* __restrict__ qg, const float* __restrict__ kg,
                       const float* __restrict__ vg, float* __restrict__ ctx) {
    __shared__ float p[T_LEN];     // 32 KB
    __shared__ float red[256];
    int h = blockIdx.x, kvh = h >> 2, tid = threadIdx.x;
    float q[HD];
#pragma unroll
    for (int d = 0; d < HD; d++) q[d] = qg[(size_t)h * HD + d];
    const float scale = rsqrtf((float)HD);

    float lm = -1e30f;
    for (int t = tid; t < T_LEN; t += 192) {
        float s = 0.f;
#pragma unroll
        for (int d = 0; d < HD; d++) s += q[d] * kg[((size_t)t * NKV + kvh) * HD + d];
        s *= scale;
        p[t] = s;
        lm = fmaxf(lm, s);
    }
    red[tid] = lm;
    if (tid < 64) red[192 + tid] = -1e30f;
    __syncthreads();
    for (int o = 128; o > 0; o >>= 1) {
        if (tid < o) red[tid] = fmaxf(red[tid], red[tid + o]);
        __syncthreads();
    }
    float m = red[0];
    __syncthreads();

    float ll = 0.f;
    for (int t = tid; t < T_LEN; t += 192) {
        float e = __expf(p[t] - m);
        p[t] = e;
        ll += e;
    }
    red[tid] = ll;
    if (tid < 64) red[192 + tid] = 0.f;
    __syncthreads();
    for (int o = 128; o > 0; o >>= 1) {
        if (tid < o) red[tid] += red[tid + o];
        __syncthreads();
    }
    float inv = 1.f / red[0];
    __syncthreads();

    int d = tid % 96, g = tid / 96;   // g in {0,1}
    float acc0 = 0.f, acc1 = 0.f, acc2 = 0.f, acc3 = 0.f;
    for (int t = g; t < T_LEN; t += 8) {
        acc0 += p[t]     * vg[((size_t)t       * NKV + kvh) * HD + d];
        acc1 += p[t + 2] * vg[((size_t)(t + 2) * NKV + kvh) * HD + d];
        acc2 += p[t + 4] * vg[((size_t)(t + 4) * NKV + kvh) * HD + d];
        acc3 += p[t + 6] * vg[((size_t)(t + 6) * NKV + kvh) * HD + d];
    }
    red[tid] = acc0 + acc1 + acc2 + acc3;
    __syncthreads();
    if (g == 0) ctx[(size_t)h * HD + d] = (red[d] + red[96 + d]) * inv;
}

// ---------------- launch ---------------------------------------------------
extern "C" void kernel_launch(void* const* d_in, const int* in_sizes, int n_in,
                              void* d_out, int out_size) {
    const float* x    = (const float*)d_in[0];
    const float* cosf = (const float*)d_in[1];
    const float* sinf = (const float*)d_in[2];
    // d_in[3] = position_ids (arange, unused)
    const float* W_qs = (const float*)d_in[4];
    const float* W_ks = (const float*)d_in[5];
    const float* W_vs = (const float*)d_in[6];
    const float* W_qg = (const float*)d_in[7];
    const float* W_kg = (const float*)d_in[8];
    const float* W_vg = (const float*)d_in[9];
    const float* W_o  = (const float*)d_in[10];
    float* out = (float*)d_out;

    float *qs, *ks, *vs, *kg, *vg, *ctx, *qg0;
    cudaGetSymbolAddress((void**)&qs,  g_qs);
    cudaGetSymbolAddress((void**)&ks,  g_ks);
    cudaGetSymbolAddress((void**)&vs,  g_vs);
    cudaGetSymbolAddress((void**)&kg,  g_kg);
    cudaGetSymbolAddress((void**)&vg,  g_vg);
    cudaGetSymbolAddress((void**)&ctx, g_ctx);
    cudaGetSymbolAddress((void**)&qg0, g_qg0);

    dim3 blk(256);
    dim3 gWide(QW / 128, T_LEN / 128);    // (12, 64)
    dim3 gNar(KVW / 128, T_LEN / 128);    // (3, 64)

    tf32_gemm<<<gWide, blk>>>(x, W_qs, qs, T_LEN, QW, DM);
    tf32_gemm<<<gNar,  blk>>>(x, W_ks, ks, T_LEN, KVW, DM);
    tf32_gemm<<<gNar,  blk>>>(x, W_vs, vs, T_LEN, KVW, DM);
    tf32_gemm<<<gNar,  blk>>>(x, W_kg, kg, T_LEN, KVW, DM);
    tf32_gemm<<<gNar,  blk>>>(x, W_vg, vg, T_LEN, KVW, DM);
    qg0_kernel<<<QW / 256, 256>>>(x, W_qg, qg0);

    int pairs16 = T_LEN * NH * (HD / 2);
    int pairs4  = T_LEN * NKV * (HD / 2);
    rope_kernel<<<(pairs16 + 255) / 256, 256>>>(qs, cosf, sinf, NH);
    rope_kernel<<<(pairs4  + 255) / 256, 256>>>(ks, cosf, sinf, NKV);
    rope_kernel<<<(pairs4  + 255) / 256, 256>>>(kg, cosf, sinf, NKV);

    int smem_attn = 2 * 128 * HD * (int)sizeof(float);  // 98304
    cudaFuncSetAttribute(local_attn_kernel,
                         cudaFuncAttributeMaxDynamicSharedMemorySize, smem_attn);
    local_attn_kernel<<<dim3(T_LEN / 128, NH), 128, smem_attn>>>(qs, ks, vs, kg, vg, ctx);

    global_row_kernel<<<NH, 192>>>(qg0, kg, vg, ctx);

    tf32_gemm<<<gWide, blk>>>(ctx, W_o, out, T_LEN, QW, DM);
}

// round 6
// speedup vs baseline: 2.1636x; 1.2239x over previous
#include <cuda_runtime.h>
#include <cuda_bf16.h>
#include <math.h>

#define T_LEN 8192
#define DM    1536
#define NH    16
#define NKV   4
#define HD    96
#define KVW   (NKV*HD)   // 384
#define QW    (NH*HD)    // 1536
#define W2    256

// ---------------- scratch (device globals; no allocation allowed) ----------
__device__ float g_qs[(size_t)T_LEN*QW];
__device__ float g_ks[(size_t)T_LEN*KVW];
__device__ float g_vs[(size_t)T_LEN*KVW];
__device__ float g_kg[(size_t)T_LEN*KVW];
__device__ float g_vg[(size_t)T_LEN*KVW];
__device__ float g_ctx[(size_t)T_LEN*QW];
__device__ float g_qg0[QW];

// ---------------- helpers ---------------------------------------------------
__device__ __forceinline__ unsigned f2tf(float x) {
    unsigned u; asm("cvt.rna.tf32.f32 %0, %1;" : "=r"(u) : "f"(x)); return u;
}
__device__ __forceinline__ void mma_tf32(float c[4], const unsigned a[4], const unsigned b[2]) {
    asm volatile("mma.sync.aligned.m16n8k8.row.col.f32.tf32.tf32.f32 "
        "{%0,%1,%2,%3}, {%4,%5,%6,%7}, {%8,%9}, {%0,%1,%2,%3};"
        : "+f"(c[0]), "+f"(c[1]), "+f"(c[2]), "+f"(c[3])
        : "r"(a[0]), "r"(a[1]), "r"(a[2]), "r"(a[3]), "r"(b[0]), "r"(b[1]));
}
__device__ __forceinline__ void cp16(void* s, const void* g) {
    unsigned sa = (unsigned)__cvta_generic_to_shared(s);
    asm volatile("cp.async.cg.shared.global [%0], [%1], 16;" :: "r"(sa), "l"(g));
}

// ---------------- TF32 GEMM body: 3-stage cp.async pipeline ----------------
// 128x128 block tile, BK=32, 256 threads (8 warps), warp tile 32x64.
#define NSTAGE 3
#define ASTR 36                  // 128 rows x 32 k, row stride 36 words
#define BSTR 136                 // 32 k x 128 cols, row stride 136 words
#define A_TILE (128*ASTR)        // 4608 floats
#define B_TILE (32*BSTR)         // 4352 floats
#define GEMM_SMEM (NSTAGE*(A_TILE+B_TILE)*4)   // 107520 bytes

__device__ __forceinline__ void gemm_body(const float* __restrict__ A,
                                          const float* __restrict__ B,
                                          float* __restrict__ C,
                                          int N, int row0, int col0) {
    extern __shared__ float sm[];
    float* As = sm;
    float* Bs = sm + NSTAGE * A_TILE;
    const int K = DM;
    int tid = threadIdx.x, lane = tid & 31, warp = tid >> 5;
    int wm = (warp >> 1) * 32, wn = (warp & 1) * 64;
    int gid = lane >> 2, qid = lane & 3;

    float c[2][8][4];
#pragma unroll
    for (int mt = 0; mt < 2; mt++)
#pragma unroll
        for (int nt = 0; nt < 8; nt++)
#pragma unroll
            for (int i = 0; i < 4; i++) c[mt][nt][i] = 0.f;

    const int nk = K / 32;   // 48

    auto load_stage = [&](int st, int k0) {
        float* Asm = As + st * A_TILE;
        float* Bsm = Bs + st * B_TILE;
#pragma unroll
        for (int i = 0; i < 4; i++) {
            int f = tid + 256 * i;
            int r = f >> 3, kq = (f & 7) * 4;
            cp16(&Asm[r * ASTR + kq], &A[(size_t)(row0 + r) * K + k0 + kq]);
        }
#pragma unroll
        for (int i = 0; i < 4; i++) {
            int f = tid + 256 * i;
            int r = f >> 5, c4 = (f & 31) * 4;
            cp16(&Bsm[r * BSTR + c4], &B[(size_t)(k0 + r) * N + col0 + c4]);
        }
        asm volatile("cp.async.commit_group;");
    };

    load_stage(0, 0);
    load_stage(1, 32);

    for (int it = 0; it < nk; it++) {
        if (it + 1 < nk) asm volatile("cp.async.wait_group 1;");
        else             asm volatile("cp.async.wait_group 0;");
        __syncthreads();
        if (it + 2 < nk) load_stage((it + 2) % NSTAGE, (it + 2) * 32);

        float* Asm = As + (it % NSTAGE) * A_TILE;
        float* Bsm = Bs + (it % NSTAGE) * B_TILE;
#pragma unroll
        for (int kk = 0; kk < 4; kk++) {
            int kb = kk * 8 + qid;
            unsigned a[2][4], b[8][2];
#pragma unroll
            for (int mt = 0; mt < 2; mt++) {
                int row = wm + mt * 16 + gid;
                a[mt][0] = f2tf(Asm[row * ASTR + kb]);
                a[mt][1] = f2tf(Asm[(row + 8) * ASTR + kb]);
                a[mt][2] = f2tf(Asm[row * ASTR + kb + 4]);
                a[mt][3] = f2tf(Asm[(row + 8) * ASTR + kb + 4]);
            }
#pragma unroll
            for (int nt = 0; nt < 8; nt++) {
                int col = wn + nt * 8 + gid;
                b[nt][0] = f2tf(Bsm[kb * BSTR + col]);
                b[nt][1] = f2tf(Bsm[(kb + 4) * BSTR + col]);
            }
#pragma unroll
            for (int mt = 0; mt < 2; mt++)
#pragma unroll
                for (int nt = 0; nt < 8; nt++)
                    mma_tf32(c[mt][nt], a[mt], b[nt]);
        }
    }
    __syncthreads();
    // epilogue
#pragma unroll
    for (int mt = 0; mt < 2; mt++) {
        int r = row0 + wm + mt * 16 + gid;
#pragma unroll
        for (int nt = 0; nt < 8; nt++) {
            int cc = col0 + wn + nt * 8 + 2 * qid;
            *(float2*)&C[(size_t)r * N + cc]       = make_float2(c[mt][nt][0], c[mt][nt][1]);
            *(float2*)&C[(size_t)(r + 8) * N + cc] = make_float2(c[mt][nt][2], c[mt][nt][3]);
        }
    }
}

// All 5 projection GEMMs fused into one launch (1536 blocks).
__global__ __launch_bounds__(256)
void proj_gemm(const float* __restrict__ x,
               const float* __restrict__ Wqs, const float* __restrict__ Wks,
               const float* __restrict__ Wvs, const float* __restrict__ Wkg,
               const float* __restrict__ Wvg,
               float* qs, float* ks, float* vs, float* kg, float* vg) {
    int id = blockIdx.x;
    const float* B; float* C; int N, rb, cb;
    if (id < 768) {
        B = Wqs; C = qs; N = QW; cb = id % 12; rb = id / 12;
    } else {
        int r = id - 768;
        int w = r / 192; r -= w * 192;
        cb = r % 3; rb = r / 3; N = KVW;
        if      (w == 0) { B = Wks; C = ks; }
        else if (w == 1) { B = Wvs; C = vs; }
        else if (w == 2) { B = Wkg; C = kg; }
        else             { B = Wvg; C = vg; }
    }
    gemm_body(x, B, C, N, rb * 128, cb * 128);
}

__global__ __launch_bounds__(256)
void out_gemm(const float* __restrict__ ctx, const float* __restrict__ Wo,
              float* __restrict__ out) {
    int id = blockIdx.x;
    int cb = id % 12, rb = id / 12;
    gemm_body(ctx, Wo, out, QW, rb * 128, cb * 128);
}

// ---------------- qg row 0 only: out[j] = x[0,:] @ W_qg[:,j] ---------------
__global__ __launch_bounds__(256)
void qg0_kernel(const float* __restrict__ x, const float* __restrict__ W,
                float* __restrict__ out) {
    __shared__ float xs[DM];
    int j = blockIdx.x * 256 + threadIdx.x;
    for (int k = threadIdx.x; k < DM; k += 256) xs[k] = x[k];
    __syncthreads();
    float a0 = 0.f, a1 = 0.f, a2 = 0.f, a3 = 0.f;
#pragma unroll 4
    for (int k = 0; k < DM; k += 4) {
        a0 += xs[k]     * W[(size_t)k       * QW + j];
        a1 += xs[k + 1] * W[(size_t)(k + 1) * QW + j];
        a2 += xs[k + 2] * W[(size_t)(k + 2) * QW + j];
        a3 += xs[k + 3] * W[(size_t)(k + 3) * QW + j];
    }
    out[j] = (a0 + a1) + (a2 + a3);
}

// ---------------- RoPE (interleaved pairs), in place on [T, H, HD] --------
__global__ void rope_kernel(float* __restrict__ x,
                            const float* __restrict__ cosf,
                            const float* __restrict__ sinf, int H) {
    int idx = blockIdx.x * blockDim.x + threadIdx.x;
    int total = T_LEN * H * (HD / 2);
    if (idx >= total) return;
    int p = idx % (HD / 2);
    int h = (idx / (HD / 2)) % H;
    int t = idx / ((HD / 2) * H);
    float c = cosf[t * (HD / 2) + p];
    float s = sinf[t * (HD / 2) + p];
    float* base = x + ((size_t)t * H + h) * HD + 2 * p;
    float xe = base[0], xo = base[1];
    base[0] = xe * c - xo * s;
    base[1] = xe * s + xo * c;
}

// ---------------- local sliding-window attention + 1 global token ---------
// block = 128 queries x 1 head, 256 threads: 2 threads per query, 48 dims each
__global__ __launch_bounds__(256)
void local_attn_kernel(const float* __restrict__ qs, const float* __restrict__ ks,
                       const float* __restrict__ vs, const float* __restrict__ kg,
                       const float* __restrict__ vg, float* __restrict__ ctx) {
    extern __shared__ float smem[];
    float* Ks = smem;                 // [128][96]
    float* Vs = smem + 128 * HD;      // [128][96]
    int tid  = threadIdx.x;
    int h    = blockIdx.y;
    int kvh  = h >> 2;
    int q0   = blockIdx.x * 128;
    int qi   = tid >> 1;              // query within block
    int half = tid & 1;               // which 48-dim half
    int t    = q0 + qi;
    int d0   = half * 48;

    float q[48], acc[48];
#pragma unroll
    for (int i = 0; i < 12; i++) {
        float4 v = *(const float4*)&qs[((size_t)t * NH + h) * HD + d0 + 4 * i];
        q[4*i] = v.x; q[4*i+1] = v.y; q[4*i+2] = v.z; q[4*i+3] = v.w;
    }
#pragma unroll
    for (int i = 0; i < 48; i++) acc[i] = 0.f;
    const float scale = rsqrtf((float)HD);
    float m = -1e30f, l = 0.f;

    for (int kt = 0; kt < 3; kt++) {
        int kstart = q0 - W2 + kt * 128;
        // 256 threads load 128 rows of K and V (24 float4 per row each)
#pragma unroll
        for (int i = 0; i < 12; i++) {
            int f = tid + 256 * i;         // 0..3071
            int r = f / 24, c4 = (f % 24) * 4;
            int krow = kstart + r;
            if (krow >= 0 && krow < T_LEN) {
                *(float4*)&Ks[r * HD + c4] = *(const float4*)&ks[((size_t)krow * NKV + kvh) * HD + c4];
                *(float4*)&Vs[r * HD + c4] = *(const float4*)&vs[((size_t)krow * NKV + kvh) * HD + c4];
            }
        }
        __syncthreads();
        for (int j = 0; j < 128; j++) {
            int kpos = kstart + j;
            float part = 0.f;
#pragma unroll
            for (int i = 0; i < 12; i++) {
                float4 kv = *(float4*)&Ks[j * HD + d0 + 4 * i];
                part += q[4*i] * kv.x + q[4*i+1] * kv.y + q[4*i+2] * kv.z + q[4*i+3] * kv.w;
            }
            float s = (part + __shfl_xor_sync(0xffffffffu, part, 1)) * scale;
            bool valid = (kpos >= 1) && (kpos <= t) && (kpos >= t - W2);
            if (valid) {
                if (s > m) {
                    float corr = __expf(m - s);
                    m = s; l *= corr;
#pragma unroll
                    for (int d = 0; d < 48; d++) acc[d] *= corr;
                }
                float p = __expf(s - m);
                l += p;
#pragma unroll
                for (int i = 0; i < 12; i++) {
                    float4 vv = *(float4*)&Vs[j * HD + d0 + 4 * i];
                    acc[4*i]   += p * vv.x; acc[4*i+1] += p * vv.y;
                    acc[4*i+2] += p * vv.z; acc[4*i+3] += p * vv.w;
                }
            }
        }
        __syncthreads();
    }
    // global key (position 0, kg/vg projections); valid for all t
    {
        float part = 0.f;
#pragma unroll
        for (int d = 0; d < 48; d++) part += q[d] * kg[(size_t)kvh * HD + d0 + d];
        float s = (part + __shfl_xor_sync(0xffffffffu, part, 1)) * scale;
        if (s > m) {
            float corr = __expf(m - s);
            m = s; l *= corr;
#pragma unroll
            for (int d = 0; d < 48; d++) acc[d] *= corr;
        }
        float p = __expf(s - m);
        l += p;
#pragma unroll
        for (int d = 0; d < 48; d++) acc[d] += p * vg[(size_t)kvh * HD + d0 + d];
    }
    float inv = 1.f / l;
#pragma unroll
    for (int i = 0; i < 12; i++) {
        float4 o = make_float4(acc[4*i] * inv, acc[4*i+1] * inv, acc[4*i+2] * inv, acc[4*i+3] * inv);
        *(float4*)&ctx[((size_t)t * NH + h) * HD + d0 + 4 * i] = o;
    }
}

// ---------------- global row: q@pos0 (qg) over all T kg keys --------------
__global__ __launch_bounds__(192)
void global_row_kernel(const float* __restrict__ qg, const float* __restrict__ kg,
                       const float* __restrict__ vg, float* __restrict__ ctx) {
    __shared__ float p[T_LEN];     // 32 KB
    __shared__ float red[256];
    int h = blockIdx.x, kvh = h >> 2, tid = threadIdx.x;
    float q[HD];
#pragma unroll
    for (int d = 0; d < HD; d++) q[d] = qg[(size_t)h * HD + d];
    const float scale = rsqrtf((float)HD);

    float lm = -1e30f;
    for (int t = tid; t < T_LEN; t += 192) {
        float s = 0.f;
#pragma unroll
        for (int d = 0; d < HD; d++) s += q[d] * kg[((size_t)t * NKV + kvh) * HD + d];
        s *= scale;
        p[t] = s;
        lm = fmaxf(lm, s);
    }
    red[tid] = lm;
    if (tid < 64) red[192 + tid] = -1e30f;
    __syncthreads();
    for (int o = 128; o > 0; o >>= 1) {
        if (tid < o) red[tid] = fmaxf(red[tid], red[tid + o]);
        __syncthreads();
    }
    float m = red[0];
    __syncthreads();

    float ll = 0.f;
    for (int t = tid; t < T_LEN; t += 192) {
        float e = __expf(p[t] - m);
        p[t] = e;
        ll += e;
    }
    red[tid] = ll;
    if (tid < 64) red[192 + tid] = 0.f;
    __syncthreads();
    for (int o = 128; o > 0; o >>= 1) {
        if (tid < o) red[tid] += red[tid + o];
        __syncthreads();
    }
    float inv = 1.f / red[0];
    __syncthreads();

    int d = tid % 96, g = tid / 96;   // g in {0,1}
    float acc0 = 0.f, acc1 = 0.f, acc2 = 0.f, acc3 = 0.f;
    for (int t = g; t < T_LEN; t += 8) {
        acc0 += p[t]     * vg[((size_t)t       * NKV + kvh) * HD + d];
        acc1 += p[t + 2] * vg[((size_t)(t + 2) * NKV + kvh) * HD + d];
        acc2 += p[t + 4] * vg[((size_t)(t + 4) * NKV + kvh) * HD + d];
        acc3 += p[t + 6] * vg[((size_t)(t + 6) * NKV + kvh) * HD + d];
    }
    red[tid] = acc0 + acc1 + acc2 + acc3;
    __syncthreads();
    if (g == 0) ctx[(size_t)h * HD + d] = (red[d] + red[96 + d]) * inv;
}

// ---------------- launch ---------------------------------------------------
extern "C" void kernel_launch(void* const* d_in, const int* in_sizes, int n_in,
                              void* d_out, int out_size) {
    const float* x    = (const float*)d_in[0];
    const float* cosf = (const float*)d_in[1];
    const float* sinf = (const float*)d_in[2];
    // d_in[3] = position_ids (arange, unused)
    const float* W_qs = (const float*)d_in[4];
    const float* W_ks = (const float*)d_in[5];
    const float* W_vs = (const float*)d_in[6];
    const float* W_qg = (const float*)d_in[7];
    const float* W_kg = (const float*)d_in[8];
    const float* W_vg = (const float*)d_in[9];
    const float* W_o  = (const float*)d_in[10];
    float* out = (float*)d_out;

    float *qs, *ks, *vs, *kg, *vg, *ctx, *qg0;
    cudaGetSymbolAddress((void**)&qs,  g_qs);
    cudaGetSymbolAddress((void**)&ks,  g_ks);
    cudaGetSymbolAddress((void**)&vs,  g_vs);
    cudaGetSymbolAddress((void**)&kg,  g_kg);
    cudaGetSymbolAddress((void**)&vg,  g_vg);
    cudaGetSymbolAddress((void**)&ctx, g_ctx);
    cudaGetSymbolAddress((void**)&qg0, g_qg0);

    cudaFuncSetAttribute(proj_gemm, cudaFuncAttributeMaxDynamicSharedMemorySize, GEMM_SMEM);
    cudaFuncSetAttribute(out_gemm,  cudaFuncAttributeMaxDynamicSharedMemorySize, GEMM_SMEM);

    proj_gemm<<<1536, 256, GEMM_SMEM>>>(x, W_qs, W_ks, W_vs, W_kg, W_vg,
                                        qs, ks, vs, kg, vg);
    qg0_kernel<<<QW / 256, 256>>>(x, W_qg, qg0);

    int pairs16 = T_LEN * NH * (HD / 2);
    int pairs4  = T_LEN * NKV * (HD / 2);
    rope_kernel<<<(pairs16 + 255) / 256, 256>>>(qs, cosf, sinf, NH);
    rope_kernel<<<(pairs4  + 255) / 256, 256>>>(ks, cosf, sinf, NKV);
    rope_kernel<<<(pairs4  + 255) / 256, 256>>>(kg, cosf, sinf, NKV);

    int smem_attn = 2 * 128 * HD * (int)sizeof(float);  // 98304
    cudaFuncSetAttribute(local_attn_kernel,
                         cudaFuncAttributeMaxDynamicSharedMemorySize, smem_attn);
    local_attn_kernel<<<dim3(T_LEN / 128, NH), 256, smem_attn>>>(qs, ks, vs, kg, vg, ctx);

    global_row_kernel<<<NH, 192>>>(qg0, kg, vg, ctx);

    out_gemm<<<768, 256, GEMM_SMEM>>>(ctx, W_o, out);
}

// round 7
// speedup vs baseline: 2.7332x; 1.2633x over previous
#include <cuda_runtime.h>
#include <cuda_bf16.h>
#include <math.h>

#define T_LEN 8192
#define DM    1536
#define NH    16
#define NKV   4
#define HD    96
#define KVW   (NKV*HD)   // 384
#define QW    (NH*HD)    // 1536
#define W2    256

// ---------------- scratch (device globals; no allocation allowed) ----------
__device__ float g_qs[(size_t)T_LEN*QW];
__device__ float g_ks[(size_t)T_LEN*KVW];
__device__ float g_vs[(size_t)T_LEN*KVW];
__device__ float g_kg[(size_t)T_LEN*KVW];
__device__ float g_vg[(size_t)T_LEN*KVW];
__device__ float g_ctx[(size_t)T_LEN*QW];
__device__ float g_qg0[QW];

// ---------------- helpers ---------------------------------------------------
__device__ __forceinline__ unsigned f2tf(float x) {
    unsigned u; asm("cvt.rna.tf32.f32 %0, %1;" : "=r"(u) : "f"(x)); return u;
}
__device__ __forceinline__ void mma_tf32(float c[4], const unsigned a[4], const unsigned b[2]) {
    asm volatile("mma.sync.aligned.m16n8k8.row.col.f32.tf32.tf32.f32 "
        "{%0,%1,%2,%3}, {%4,%5,%6,%7}, {%8,%9}, {%0,%1,%2,%3};"
        : "+f"(c[0]), "+f"(c[1]), "+f"(c[2]), "+f"(c[3])
        : "r"(a[0]), "r"(a[1]), "r"(a[2]), "r"(a[3]), "r"(b[0]), "r"(b[1]));
}
__device__ __forceinline__ void cp16(void* s, const void* g) {
    unsigned sa = (unsigned)__cvta_generic_to_shared(s);
    asm volatile("cp.async.cg.shared.global [%0], [%1], 16;" :: "r"(sa), "l"(g));
}

// ---------------- TF32 GEMM body: 3-stage cp.async pipeline ----------------
#define NSTAGE 3
#define ASTR 36
#define BSTR 136
#define A_TILE (128*ASTR)
#define B_TILE (32*BSTR)
#define GEMM_SMEM (NSTAGE*(A_TILE+B_TILE)*4)   // 107520 bytes

__device__ __forceinline__ void gemm_body(const float* __restrict__ A,
                                          const float* __restrict__ B,
                                          float* __restrict__ C,
                                          int N, int row0, int col0) {
    extern __shared__ float sm[];
    float* As = sm;
    float* Bs = sm + NSTAGE * A_TILE;
    const int K = DM;
    int tid = threadIdx.x, lane = tid & 31, warp = tid >> 5;
    int wm = (warp >> 1) * 32, wn = (warp & 1) * 64;
    int gid = lane >> 2, qid = lane & 3;

    float c[2][8][4];
#pragma unroll
    for (int mt = 0; mt < 2; mt++)
#pragma unroll
        for (int nt = 0; nt < 8; nt++)
#pragma unroll
            for (int i = 0; i < 4; i++) c[mt][nt][i] = 0.f;

    const int nk = K / 32;

    auto load_stage = [&](int st, int k0) {
        float* Asm = As + st * A_TILE;
        float* Bsm = Bs + st * B_TILE;
#pragma unroll
        for (int i = 0; i < 4; i++) {
            int f = tid + 256 * i;
            int r = f >> 3, kq = (f & 7) * 4;
            cp16(&Asm[r * ASTR + kq], &A[(size_t)(row0 + r) * K + k0 + kq]);
        }
#pragma unroll
        for (int i = 0; i < 4; i++) {
            int f = tid + 256 * i;
            int r = f >> 5, c4 = (f & 31) * 4;
            cp16(&Bsm[r * BSTR + c4], &B[(size_t)(k0 + r) * N + col0 + c4]);
        }
        asm volatile("cp.async.commit_group;");
    };

    load_stage(0, 0);
    load_stage(1, 32);

    for (int it = 0; it < nk; it++) {
        if (it + 1 < nk) asm volatile("cp.async.wait_group 1;");
        else             asm volatile("cp.async.wait_group 0;");
        __syncthreads();
        if (it + 2 < nk) load_stage((it + 2) % NSTAGE, (it + 2) * 32);

        float* Asm = As + (it % NSTAGE) * A_TILE;
        float* Bsm = Bs + (it % NSTAGE) * B_TILE;
#pragma unroll
        for (int kk = 0; kk < 4; kk++) {
            int kb = kk * 8 + qid;
            unsigned a[2][4], b[8][2];
#pragma unroll
            for (int mt = 0; mt < 2; mt++) {
                int row = wm + mt * 16 + gid;
                a[mt][0] = f2tf(Asm[row * ASTR + kb]);
                a[mt][1] = f2tf(Asm[(row + 8) * ASTR + kb]);
                a[mt][2] = f2tf(Asm[row * ASTR + kb + 4]);
                a[mt][3] = f2tf(Asm[(row + 8) * ASTR + kb + 4]);
            }
#pragma unroll
            for (int nt = 0; nt < 8; nt++) {
                int col = wn + nt * 8 + gid;
                b[nt][0] = f2tf(Bsm[kb * BSTR + col]);
                b[nt][1] = f2tf(Bsm[(kb + 4) * BSTR + col]);
            }
#pragma unroll
            for (int mt = 0; mt < 2; mt++)
#pragma unroll
                for (int nt = 0; nt < 8; nt++)
                    mma_tf32(c[mt][nt], a[mt], b[nt]);
        }
    }
    __syncthreads();
#pragma unroll
    for (int mt = 0; mt < 2; mt++) {
        int r = row0 + wm + mt * 16 + gid;
#pragma unroll
        for (int nt = 0; nt < 8; nt++) {
            int cc = col0 + wn + nt * 8 + 2 * qid;
            *(float2*)&C[(size_t)r * N + cc]       = make_float2(c[mt][nt][0], c[mt][nt][1]);
            *(float2*)&C[(size_t)(r + 8) * N + cc] = make_float2(c[mt][nt][2], c[mt][nt][3]);
        }
    }
}

__global__ __launch_bounds__(256)
void proj_gemm(const float* __restrict__ x,
               const float* __restrict__ Wqs, const float* __restrict__ Wks,
               const float* __restrict__ Wvs, const float* __restrict__ Wkg,
               const float* __restrict__ Wvg,
               float* qs, float* ks, float* vs, float* kg, float* vg) {
    int id = blockIdx.x;
    const float* B; float* C; int N, rb, cb;
    if (id < 768) {
        B = Wqs; C = qs; N = QW; cb = id % 12; rb = id / 12;
    } else {
        int r = id - 768;
        int w = r / 192; r -= w * 192;
        cb = r % 3; rb = r / 3; N = KVW;
        if      (w == 0) { B = Wks; C = ks; }
        else if (w == 1) { B = Wvs; C = vs; }
        else if (w == 2) { B = Wkg; C = kg; }
        else             { B = Wvg; C = vg; }
    }
    gemm_body(x, B, C, N, rb * 128, cb * 128);
}

__global__ __launch_bounds__(256)
void out_gemm(const float* __restrict__ ctx, const float* __restrict__ Wo,
              float* __restrict__ out) {
    int id = blockIdx.x;
    int cb = id % 12, rb = id / 12;
    gemm_body(ctx, Wo, out, QW, rb * 128, cb * 128);
}

// ---------------- qg row 0 only ---------------------------------------------
__global__ __launch_bounds__(256)
void qg0_kernel(const float* __restrict__ x, const float* __restrict__ W,
                float* __restrict__ out) {
    __shared__ float xs[DM];
    int j = blockIdx.x * 256 + threadIdx.x;
    for (int k = threadIdx.x; k < DM; k += 256) xs[k] = x[k];
    __syncthreads();
    float a0 = 0.f, a1 = 0.f, a2 = 0.f, a3 = 0.f;
#pragma unroll 4
    for (int k = 0; k < DM; k += 4) {
        a0 += xs[k]     * W[(size_t)k       * QW + j];
        a1 += xs[k + 1] * W[(size_t)(k + 1) * QW + j];
        a2 += xs[k + 2] * W[(size_t)(k + 2) * QW + j];
        a3 += xs[k + 3] * W[(size_t)(k + 3) * QW + j];
    }
    out[j] = (a0 + a1) + (a2 + a3);
}

// ---------------- RoPE ------------------------------------------------------
__global__ void rope_kernel(float* __restrict__ x,
                            const float* __restrict__ cosf,
                            const float* __restrict__ sinf, int H) {
    int idx = blockIdx.x * blockDim.x + threadIdx.x;
    int total = T_LEN * H * (HD / 2);
    if (idx >= total) return;
    int p = idx % (HD / 2);
    int h = (idx / (HD / 2)) % H;
    int t = idx / ((HD / 2) * H);
    float c = cosf[t * (HD / 2) + p];
    float s = sinf[t * (HD / 2) + p];
    float* base = x + ((size_t)t * H + h) * HD + 2 * p;
    float xe = base[0], xo = base[1];
    base[0] = xe * c - xo * s;
    base[1] = xe * s + xo * c;
}

// ---------------- tensor-core flash attention (local window + global key) --
// block = 128 queries x 1 head, 256 threads (8 warps x 16 query rows).
// Smem strides chosen for conflict-free mma fragment loads:
//   Q/K stride 100 (bank=4g+q), V stride 104 (bank=8q+g), P stride 132.
#define QSTR 100
#define KSTR 100
#define VSTR 104
#define PSTR 132
#define ATTN_SMEM ((128*QSTR + 128*KSTR + 128*VSTR + 128*PSTR + 128 + 96) * 4)  // 224128

__global__ __launch_bounds__(256)
void flash_attn_kernel(const float* __restrict__ qs_g, const float* __restrict__ ks_g,
                       const float* __restrict__ vs_g, const float* __restrict__ kg,
                       const float* __restrict__ vg, float* __restrict__ ctx) {
    extern __shared__ unsigned smu[];
    unsigned* Qs = smu;                       // [128][QSTR] tf32 bits
    unsigned* Ks = Qs + 128 * QSTR;           // [128][KSTR]
    unsigned* Vs = Ks + 128 * KSTR;           // [128][VSTR]
    unsigned* Ps = Vs + 128 * VSTR;           // [128][PSTR]
    float* sg  = (float*)(Ps + 128 * PSTR);   // [128] global-key scores
    float* vgs = sg + 128;                    // [96]

    int tid = threadIdx.x, lane = tid & 31, warp = tid >> 5;
    int gid = lane >> 2, qid = lane & 3;
    int h = blockIdx.y, kvh = h >> 2;
    int q0 = blockIdx.x * 128;
    const float scale = rsqrtf((float)HD);
    int row = warp * 16 + gid;                // this thread covers rows row, row+8

    // ---- load Q tile into smem (tf32), 3072 float4 slots ----
#pragma unroll
    for (int i = 0; i < 12; i++) {
        int f = tid + 256 * i;
        int r = f / 24, c4 = (f % 24) * 4;
        float4 v = *(const float4*)&qs_g[((size_t)(q0 + r) * NH + h) * HD + c4];
        unsigned* p = &Qs[r * QSTR + c4];
        p[0] = f2tf(v.x); p[1] = f2tf(v.y); p[2] = f2tf(v.z); p[3] = f2tf(v.w);
    }
    // ---- global-key scores: 2 threads per row ----
    {
        int qi = tid >> 1, half = tid & 1;
        float part = 0.f;
        const float* qrow = &qs_g[((size_t)(q0 + qi) * NH + h) * HD + half * 48];
        const float* krow = &kg[(size_t)kvh * HD + half * 48];
#pragma unroll
        for (int d = 0; d < 48; d++) part += qrow[d] * krow[d];
        part += __shfl_xor_sync(0xffffffffu, part, 1);
        if (half == 0) sg[qi] = part * scale;
    }
    if (tid < 96) vgs[tid] = vg[(size_t)kvh * HD + tid];

    float m0 = -1e9f, m1 = -1e9f, l0 = 0.f, l1 = 0.f;
    float o[12][4];
#pragma unroll
    for (int nt = 0; nt < 12; nt++)
#pragma unroll
        for (int i = 0; i < 4; i++) o[nt][i] = 0.f;

    __syncthreads();

    for (int kt = 0; kt < 3; kt++) {
        int kstart = q0 - W2 + kt * 128;
        // ---- load K/V tile (zero-fill out-of-range rows) ----
#pragma unroll
        for (int i = 0; i < 12; i++) {
            int f = tid + 256 * i;
            int r = f / 24, c4 = (f % 24) * 4;
            int krow = kstart + r;
            float4 kv = make_float4(0.f, 0.f, 0.f, 0.f), vv = kv;
            if (krow >= 0) {
                kv = *(const float4*)&ks_g[((size_t)krow * NKV + kvh) * HD + c4];
                vv = *(const float4*)&vs_g[((size_t)krow * NKV + kvh) * HD + c4];
            }
            unsigned* pk = &Ks[r * KSTR + c4];
            pk[0] = f2tf(kv.x); pk[1] = f2tf(kv.y); pk[2] = f2tf(kv.z); pk[3] = f2tf(kv.w);
            unsigned* pv = &Vs[r * VSTR + c4];
            pv[0] = f2tf(vv.x); pv[1] = f2tf(vv.y); pv[2] = f2tf(vv.z); pv[3] = f2tf(vv.w);
        }
        __syncthreads();

        // ---- phase A: S = Q @ K^T  (16 n-tiles of 8 keys, 12 k-steps) ----
        float s[16][4];
#pragma unroll
        for (int nt = 0; nt < 16; nt++)
#pragma unroll
            for (int i = 0; i < 4; i++) s[nt][i] = 0.f;
#pragma unroll
        for (int ks = 0; ks < 12; ks++) {
            unsigned a[4];
            a[0] = Qs[row * QSTR + ks * 8 + qid];
            a[1] = Qs[(row + 8) * QSTR + ks * 8 + qid];
            a[2] = Qs[row * QSTR + ks * 8 + qid + 4];
            a[3] = Qs[(row + 8) * QSTR + ks * 8 + qid + 4];
#pragma unroll
            for (int nt = 0; nt < 16; nt++) {
                unsigned b[2];
                int col = nt * 8 + gid;
                b[0] = Ks[col * KSTR + ks * 8 + qid];
                b[1] = Ks[col * KSTR + ks * 8 + qid + 4];
                mma_tf32(s[nt], a, b);
            }
        }

        // ---- mask + online softmax (row state in 4 qid-lanes) ----
        int t0 = q0 + row, t1 = t0 + 8;
        float tmax0 = -1e9f, tmax1 = -1e9f;
#pragma unroll
        for (int nt = 0; nt < 16; nt++) {
            int cb = kstart + nt * 8 + 2 * qid;
#pragma unroll
            for (int cc = 0; cc < 2; cc++) {
                int kp = cb + cc;
                bool v0 = (kp >= 1) && (kp <= t0) && (kp >= t0 - W2);
                bool v1 = (kp >= 1) && (kp <= t1) && (kp >= t1 - W2);
                s[nt][cc]     = v0 ? s[nt][cc] * scale     : -1e9f;
                s[nt][cc + 2] = v1 ? s[nt][cc + 2] * scale : -1e9f;
                tmax0 = fmaxf(tmax0, s[nt][cc]);
                tmax1 = fmaxf(tmax1, s[nt][cc + 2]);
            }
        }
        tmax0 = fmaxf(tmax0, __shfl_xor_sync(0xffffffffu, tmax0, 1));
        tmax0 = fmaxf(tmax0, __shfl_xor_sync(0xffffffffu, tmax0, 2));
        tmax1 = fmaxf(tmax1, __shfl_xor_sync(0xffffffffu, tmax1, 1));
        tmax1 = fmaxf(tmax1, __shfl_xor_sync(0xffffffffu, tmax1, 2));
        float mn0 = fmaxf(m0, tmax0), mn1 = fmaxf(m1, tmax1);
        float corr0 = __expf(m0 - mn0), corr1 = __expf(m1 - mn1);
        l0 *= corr0; l1 *= corr1;
#pragma unroll
        for (int nt = 0; nt < 12; nt++) {
            o[nt][0] *= corr0; o[nt][1] *= corr0;
            o[nt][2] *= corr1; o[nt][3] *= corr1;
        }
        float sum0 = 0.f, sum1 = 0.f;
#pragma unroll
        for (int nt = 0; nt < 16; nt++) {
            int cb = nt * 8 + 2 * qid;
#pragma unroll
            for (int cc = 0; cc < 2; cc++) {
                float p0 = __expf(s[nt][cc] - mn0);
                float p1 = __expf(s[nt][cc + 2] - mn1);
                sum0 += p0; sum1 += p1;
                Ps[row * PSTR + cb + cc]       = f2tf(p0);
                Ps[(row + 8) * PSTR + cb + cc] = f2tf(p1);
            }
        }
        sum0 += __shfl_xor_sync(0xffffffffu, sum0, 1);
        sum0 += __shfl_xor_sync(0xffffffffu, sum0, 2);
        sum1 += __shfl_xor_sync(0xffffffffu, sum1, 1);
        sum1 += __shfl_xor_sync(0xffffffffu, sum1, 2);
        l0 += sum0; l1 += sum1;
        m0 = mn0; m1 = mn1;
        __syncwarp();   // Ps rows are warp-private

        // ---- phase B: O += P @ V  (12 dim-tiles, 16 k-steps of 8 keys) ----
#pragma unroll
        for (int ks = 0; ks < 16; ks++) {
            unsigned a[4];
            a[0] = Ps[row * PSTR + ks * 8 + qid];
            a[1] = Ps[(row + 8) * PSTR + ks * 8 + qid];
            a[2] = Ps[row * PSTR + ks * 8 + qid + 4];
            a[3] = Ps[(row + 8) * PSTR + ks * 8 + qid + 4];
#pragma unroll
            for (int nt = 0; nt < 12; nt++) {
                unsigned b[2];
                int col = nt * 8 + gid;
                b[0] = Vs[(ks * 8 + qid) * VSTR + col];
                b[1] = Vs[(ks * 8 + qid + 4) * VSTR + col];
                mma_tf32(o[nt], a, b);
            }
        }
        __syncthreads();   // before next tile overwrites Ks/Vs
    }

    // ---- global key (position 0) ----
    {
        float sg0 = sg[row], sg1 = sg[row + 8];
        float mn0 = fmaxf(m0, sg0), mn1 = fmaxf(m1, sg1);
        float corr0 = __expf(m0 - mn0), corr1 = __expf(m1 - mn1);
        float pg0 = __expf(sg0 - mn0), pg1 = __expf(sg1 - mn1);
        l0 = l0 * corr0 + pg0;
        l1 = l1 * corr1 + pg1;
        float inv0 = 1.f / l0, inv1 = 1.f / l1;
        int t0 = q0 + row, t1 = t0 + 8;
#pragma unroll
        for (int nt = 0; nt < 12; nt++) {
            int d = nt * 8 + 2 * qid;
            float v0 = vgs[d], v1 = vgs[d + 1];
            float2 r0 = make_float2((o[nt][0] * corr0 + pg0 * v0) * inv0,
                                    (o[nt][1] * corr0 + pg0 * v1) * inv0);
            float2 r1 = make_float2((o[nt][2] * corr1 + pg1 * v0) * inv1,
                                    (o[nt][3] * corr1 + pg1 * v1) * inv1);
            *(float2*)&ctx[((size_t)t0 * NH + h) * HD + d] = r0;
            *(float2*)&ctx[((size_t)t1 * NH + h) * HD + d] = r1;
        }
    }
}

// ---------------- global row: q@pos0 (qg) over all T kg keys --------------
__global__ __launch_bounds__(192)
void global_row_kernel(const float* __restrict__ qg, const float* __restrict__ kg,
                       const float* __restrict__ vg, float* __restrict__ ctx) {
    __shared__ float p[T_LEN];
    __shared__ float red[256];
    int h = blockIdx.x, kvh = h >> 2, tid = threadIdx.x;
    float q[HD];
#pragma unroll
    for (int d = 0; d < HD; d++) q[d] = qg[(size_t)h * HD + d];
    const float scale = rsqrtf((float)HD);

    float lm = -1e30f;
    for (int t = tid; t < T_LEN; t += 192) {
        float s = 0.f;
#pragma unroll
        for (int d = 0; d < HD; d++) s += q[d] * kg[((size_t)t * NKV + kvh) * HD + d];
        s *= scale;
        p[t] = s;
        lm = fmaxf(lm, s);
    }
    red[tid] = lm;
    if (tid < 64) red[192 + tid] = -1e30f;
    __syncthreads();
    for (int o = 128; o > 0; o >>= 1) {
        if (tid < o) red[tid] = fmaxf(red[tid], red[tid + o]);
        __syncthreads();
    }
    float m = red[0];
    __syncthreads();

    float ll = 0.f;
    for (int t = tid; t < T_LEN; t += 192) {
        float e = __expf(p[t] - m);
        p[t] = e;
        ll += e;
    }
    red[tid] = ll;
    if (tid < 64) red[192 + tid] = 0.f;
    __syncthreads();
    for (int o = 128; o > 0; o >>= 1) {
        if (tid < o) red[tid] += red[tid + o];
        __syncthreads();
    }
    float inv = 1.f / red[0];
    __syncthreads();

    int d = tid % 96, g = tid / 96;
    float acc0 = 0.f, acc1 = 0.f, acc2 = 0.f, acc3 = 0.f;
    for (int t = g; t < T_LEN; t += 8) {
        acc0 += p[t]     * vg[((size_t)t       * NKV + kvh) * HD + d];
        acc1 += p[t + 2] * vg[((size_t)(t + 2) * NKV + kvh) * HD + d];
        acc2 += p[t + 4] * vg[((size_t)(t + 4) * NKV + kvh) * HD + d];
        acc3 += p[t + 6] * vg[((size_t)(t + 6) * NKV + kvh) * HD + d];
    }
    red[tid] = acc0 + acc1 + acc2 + acc3;
    __syncthreads();
    if (g == 0) ctx[(size_t)h * HD + d] = (red[d] + red[96 + d]) * inv;
}

// ---------------- launch ---------------------------------------------------
extern "C" void kernel_launch(void* const* d_in, const int* in_sizes, int n_in,
                              void* d_out, int out_size) {
    const float* x    = (const float*)d_in[0];
    const float* cosf = (const float*)d_in[1];
    const float* sinf = (const float*)d_in[2];
    // d_in[3] = position_ids (arange, unused)
    const float* W_qs = (const float*)d_in[4];
    const float* W_ks = (const float*)d_in[5];
    const float* W_vs = (const float*)d_in[6];
    const float* W_qg = (const float*)d_in[7];
    const float* W_kg = (const float*)d_in[8];
    const float* W_vg = (const float*)d_in[9];
    const float* W_o  = (const float*)d_in[10];
    float* out = (float*)d_out;

    float *qs, *ks, *vs, *kg, *vg, *ctx, *qg0;
    cudaGetSymbolAddress((void**)&qs,  g_qs);
    cudaGetSymbolAddress((void**)&ks,  g_ks);
    cudaGetSymbolAddress((void**)&vs,  g_vs);
    cudaGetSymbolAddress((void**)&kg,  g_kg);
    cudaGetSymbolAddress((void**)&vg,  g_vg);
    cudaGetSymbolAddress((void**)&ctx, g_ctx);
    cudaGetSymbolAddress((void**)&qg0, g_qg0);

    cudaFuncSetAttribute(proj_gemm, cudaFuncAttributeMaxDynamicSharedMemorySize, GEMM_SMEM);
    cudaFuncSetAttribute(out_gemm,  cudaFuncAttributeMaxDynamicSharedMemorySize, GEMM_SMEM);
    cudaFuncSetAttribute(flash_attn_kernel, cudaFuncAttributeMaxDynamicSharedMemorySize, ATTN_SMEM);

    proj_gemm<<<1536, 256, GEMM_SMEM>>>(x, W_qs, W_ks, W_vs, W_kg, W_vg,
                                        qs, ks, vs, kg, vg);
    qg0_kernel<<<QW / 256, 256>>>(x, W_qg, qg0);

    int pairs16 = T_LEN * NH * (HD / 2);
    int pairs4  = T_LEN * NKV * (HD / 2);
    rope_kernel<<<(pairs16 + 255) / 256, 256>>>(qs, cosf, sinf, NH);
    rope_kernel<<<(pairs4  + 255) / 256, 256>>>(ks, cosf, sinf, NKV);
    rope_kernel<<<(pairs4  + 255) / 256, 256>>>(kg, cosf, sinf, NKV);

    flash_attn_kernel<<<dim3(T_LEN / 128, NH), 256, ATTN_SMEM>>>(qs, ks, vs, kg, vg, ctx);

    global_row_kernel<<<NH, 192>>>(qg0, kg, vg, ctx);

    out_gemm<<<768, 256, GEMM_SMEM>>>(ctx, W_o, out);
}